// round 13
// baseline (speedup 1.0000x reference)
#include <cuda_runtime.h>
#include <math.h>

#define B_CHAIN 16384
#define S_SIDE  15
#define NATM    (1 + B_CHAIN + B_CHAIN * S_SIDE)
#define NBLK_BB 128
#define NBLK_SC 512
#define NBLK    (NBLK_BB + NBLK_SC)

// 3x4 affine transform: rotation r[9] row-major, translation t[3]
struct M34 { float r[9]; float t[3]; };

__device__ __forceinline__ M34 m_identity() {
    M34 m;
    m.r[0]=1.f; m.r[1]=0.f; m.r[2]=0.f;
    m.r[3]=0.f; m.r[4]=1.f; m.r[5]=0.f;
    m.r[6]=0.f; m.r[7]=0.f; m.r[8]=1.f;
    m.t[0]=0.f; m.t[1]=0.f; m.t[2]=0.f;
    return m;
}

// C = A @ B  (A is the earlier transform)
__device__ __forceinline__ M34 compose(const M34& A, const M34& B) {
    M34 C;
#pragma unroll
    for (int i = 0; i < 3; i++) {
#pragma unroll
        for (int j = 0; j < 3; j++) {
            C.r[i*3+j] = fmaf(A.r[i*3+0], B.r[0*3+j],
                          fmaf(A.r[i*3+1], B.r[1*3+j],
                               A.r[i*3+2] * B.r[2*3+j]));
        }
        C.t[i] = fmaf(A.r[i*3+0], B.t[0],
                  fmaf(A.r[i*3+1], B.t[1],
                   fmaf(A.r[i*3+2], B.t[2], A.t[i])));
    }
    return C;
}

__device__ __forceinline__ M34 shflup(const M34& v, int d, int width) {
    M34 o;
#pragma unroll
    for (int k = 0; k < 9; k++) o.r[k] = __shfl_up_sync(0xffffffffu, v.r[k], d, width);
#pragma unroll
    for (int k = 0; k < 3; k++) o.t[k] = __shfl_up_sync(0xffffffffu, v.t[k], d, width);
    return o;
}

// FMA-pipe sincos: magic-number quadrant reduction + cephes minimax polys.
// Valid for |x| << 2^22 (here |x| < 3). Max err ~1.2e-7.
__device__ __forceinline__ void poly_sincos(float x, float* sp, float* cp) {
    const float MAGIC = 12582912.0f;             // 1.5 * 2^23
    float k = fmaf(x, 0.63661977236758134f, MAGIC);
    int   q = __float_as_int(k);
    float n = k - MAGIC;
    float r = fmaf(n, -1.57079637e+00f, x);      // pi/2 hi
    r       = fmaf(n,  4.37113883e-08f, r);      // pi/2 lo correction
    float z = r * r;
    float ps = fmaf(z, fmaf(z, -1.9515295891e-4f, 8.3321608736e-3f), -1.6666654611e-1f);
    ps = fmaf(ps * z, r, r);
    float pc = fmaf(z, fmaf(z, 2.44331571e-5f, -1.38873163e-3f), 4.16666457e-2f);
    pc = fmaf(pc, z * z, fmaf(-0.5f, z, 1.0f));
    bool swap = (q & 1);
    float s = swap ? pc : ps;
    float c = swap ? ps : pc;
    if (q & 2) s = -s;
    if ((q + 1) & 2) c = -c;
    *sp = s; *cp = c;
}

// Bond matrix: Rx(a)*Rz(b)*T(c,0,0)*Rx(d) given sin/cos of the three angles.
__device__ __forceinline__ M34 bond_mat(float sa, float ca, float sb, float cb,
                                        float sd, float cd, float c) {
    M34 m;
    m.r[0] = cb;      m.r[1] = -cd * sb;                 m.r[2] = sd * sb;
    m.r[3] = ca * sb; m.r[4] = fmaf(cd*ca, cb, -sd*sa);  m.r[5] = fmaf(-sd*ca, cb, -cd*sa);
    m.r[6] = sa * sb; m.r[7] = fmaf(cd*sa, cb,  sd*ca);  m.r[8] = fmaf(-sd*sa, cb,  cd*ca);
    m.t[0] = c * cb;
    m.t[1] = c * ca * sb;
    m.t[2] = c * sa * sb;
    return m;
}

// Fast bond build (poly sincos, FMA pipe)
__device__ __forceinline__ M34 build_bond_fast(int n, const float* __restrict__ dofs) {
    float4 dv = *(const float4*)(dofs + 4 * (n - 1));
    float sa, ca, sb, cb, sd, cd;
    poly_sincos(dv.x, &sa, &ca);
    poly_sincos(dv.y, &sb, &cb);
    poly_sincos(dv.w, &sd, &cd);
    return bond_mat(sa, ca, sb, cb, sd, cd, dv.z);
}

// Jump build (only node 1; e = full[n][5], f = full[n][4])
__device__ __forceinline__ M34 build_jump(int n,
                                          const float* __restrict__ dofs,
                                          const float* __restrict__ full_dofs) {
    float4 dv = *(const float4*)(dofs + 4 * (n - 1));
    float f = full_dofs[9 * n + 4];
    float e = full_dofs[9 * n + 5];
    float sd, cd, sf, cf, se, ce;
    poly_sincos(dv.w, &sd, &cd);
    poly_sincos(f, &sf, &cf);
    poly_sincos(e, &se, &ce);
    M34 m;
    m.r[0] = ce * cf;  m.r[1] = fmaf(sd*ce, sf, -cd*se);  m.r[2] = fmaf(cd*ce, sf,  sd*se);
    m.r[3] = se * cf;  m.r[4] = fmaf(sd*se, sf,  cd*ce);  m.r[5] = fmaf(cd*se, sf, -sd*ce);
    m.r[6] = -sf;      m.r[7] = sd * cf;                  m.r[8] = cd * cf;
    m.t[0] = dv.x; m.t[1] = dv.y; m.t[2] = dv.z;
    return m;
}

// Scratch (allocation-free: __device__ globals)
__device__ float g_G[12][B_CHAIN];     // backbone GLOBAL transforms (SoA)
__device__ float g_Agg[128][12];       // per-backbone-block aggregates
__device__ int   g_aflag[NBLK_BB][32]; // aggregate-ready flags (one line each)
__device__ int   g_cflag[NBLK_BB][32]; // chunk-globals-ready flags (one line each)
__device__ unsigned int g_cnt_all;     // all blocks completed (self-reset)

__device__ __forceinline__ int ld_acquire(int* p) {
    int v;
    asm volatile("ld.acquire.gpu.global.b32 %0, [%1];" : "=r"(v) : "l"(p) : "memory");
    return v;
}
__device__ __forceinline__ void st_release(int* p, int v) {
    asm volatile("st.release.gpu.global.b32 [%0], %1;" :: "l"(p), "r"(v) : "memory");
}

// Inclusive Kogge-Stone scan across 128 threads (4 warps)
__device__ __forceinline__ void block_scan_128(M34& v, int tid, M34* sAgg) {
    int lane = tid & 31, w = tid >> 5;
#pragma unroll
    for (int d = 1; d < 32; d <<= 1) {
        M34 o = shflup(v, d, 32);
        if (lane >= d) v = compose(o, v);
    }
    if (lane == 31) sAgg[w] = v;
    __syncthreads();
    if (w > 0) {
        M34 p = sAgg[0];
        for (int k = 1; k < w; k++) p = compose(p, sAgg[k]);
        v = compose(p, v);
    }
}

// Single fused kernel, decoupled aggregate-broadcast:
//  - each backbone block publishes its aggregate + own flag (no counter)
//  - EVERY backbone block polls all 128 flags (thread tid -> flag tid) and
//    self-scans the aggregates: no designated block, no g_P round trip
//  - per-chunk release wakes side blocks progressively
// launch_bounds(128,5): capacity 740 >= 640 -> all co-resident, no deadlock.
__global__ void __launch_bounds__(128, 5)
k_fused(const float* __restrict__ dofs,
        const float* __restrict__ full_dofs,
        const int* __restrict__ kin_id,
        float* __restrict__ out) {
    __shared__ M34 sAgg[4];
    __shared__ float sP[12];
    int blk = blockIdx.x;
    int tid = threadIdx.x;

    if (blk < NBLK_BB) {
        // ---------------- backbone ----------------
        int t = blk * 128 + tid;       // 0..16383
        int n = t + 1;                 // backbone node; n==1 is the jump node
        int kid = kin_id[n];           // prefetch
        M34 v = (n == 1) ? build_jump(n, dofs, full_dofs)
                         : build_bond_fast(n, dofs);
        block_scan_128(v, tid, sAgg);
        if (tid == 127) {
#pragma unroll
            for (int c = 0; c < 9; c++) g_Agg[blk][c] = v.r[c];
#pragma unroll
            for (int c = 0; c < 3; c++) g_Agg[blk][9 + c] = v.t[c];
            __threadfence();
        }
        __syncthreads();
        if (tid == 0) st_release(&g_aflag[blk][0], 1);   // publish own aggregate

        // poll ALL aggregate flags in parallel (thread tid -> flag tid)
        while (ld_acquire(&g_aflag[tid][0]) == 0) __nanosleep(32);
        __syncthreads();

        // self-scan the 128 aggregates -> exclusive prefix for this block
        M34 a;
#pragma unroll
        for (int c = 0; c < 9; c++) a.r[c] = __ldcg(&g_Agg[tid][c]);
#pragma unroll
        for (int c = 0; c < 3; c++) a.t[c] = __ldcg(&g_Agg[tid][9 + c]);
        block_scan_128(a, tid, sAgg);
        if (blk == 0) {
            if (tid == 0) {
#pragma unroll
                for (int c = 0; c < 12; c++) sP[c] = (c == 0 || c == 4 || c == 8) ? 1.f : 0.f;
            }
        } else if (tid == blk - 1) {
#pragma unroll
            for (int c = 0; c < 9; c++) sP[c] = a.r[c];
#pragma unroll
            for (int c = 0; c < 3; c++) sP[9 + c] = a.t[c];
        }
        __syncthreads();

        M34 P;
#pragma unroll
        for (int c = 0; c < 9; c++) P.r[c] = sP[c];
#pragma unroll
        for (int c = 0; c < 3; c++) P.t[c] = sP[9 + c];
        M34 G = compose(P, v);
        out[3 * kid + 0] = G.t[0];
        out[3 * kid + 1] = G.t[1];
        out[3 * kid + 2] = G.t[2];
#pragma unroll
        for (int c = 0; c < 9; c++) g_G[c][t] = G.r[c];
#pragma unroll
        for (int c = 0; c < 3; c++) g_G[9 + c][t] = G.t[c];
        __threadfence();
        __syncthreads();
        if (tid == 0) st_release(&g_cflag[blk][0], 1);   // release THIS chunk
    } else {
        // ------- side chains: 4 lanes/chain (ILP-batched builds) -------
        int sblk  = blk - NBLK_BB;           // 0..511
        int lane4 = tid & 3;
        int chain = sblk * 32 + (tid >> 2);  // 0..16383 (32 chains/block, one chunk)
        int chunk = sblk >> 2;
        int base  = lane4 * 4;
        int cnt   = (lane4 == 3) ? 3 : 4;    // 4+4+4+3 = 15 atoms
        int a0    = 1 + B_CHAIN + chain * S_SIDE + base;

        // prefetch all dv (4 independent LDG.128, clamped in-bounds)
        float4 dv[4];
#pragma unroll
        for (int i = 0; i < 4; i++) {
            int ns = a0 + i;
            if (ns > NATM - 1) ns = NATM - 1;
            dv[i] = *(const float4*)(dofs + 4 * (ns - 1));
        }
        int kid[4];
#pragma unroll
        for (int i = 0; i < 4; i++) {
            int ns = a0 + i;
            if (ns > NATM - 1) ns = NATM - 1;
            kid[i] = kin_id[ns];
        }

        // 12 independent sincos up-front (ILP)
        float sc[4][6];
#pragma unroll
        for (int i = 0; i < 4; i++) {
            poly_sincos(dv[i].x, &sc[i][0], &sc[i][1]);
            poly_sincos(dv[i].y, &sc[i][2], &sc[i][3]);
            poly_sincos(dv[i].w, &sc[i][4], &sc[i][5]);
        }

        float tr[4][3];
        M34 run = bond_mat(sc[0][0], sc[0][1], sc[0][2], sc[0][3],
                           sc[0][4], sc[0][5], dv[0].z);
        tr[0][0] = run.t[0]; tr[0][1] = run.t[1]; tr[0][2] = run.t[2];
#pragma unroll
        for (int i = 1; i < 4; i++) {
            M34 h = bond_mat(sc[i][0], sc[i][1], sc[i][2], sc[i][3],
                             sc[i][4], sc[i][5], dv[i].z);
            if (i < cnt) {
                run = compose(run, h);
                tr[i][0] = run.t[0]; tr[i][1] = run.t[1]; tr[i][2] = run.t[2];
            }
        }

        // inclusive scan over the 4 lanes of this chain
#pragma unroll
        for (int d = 1; d < 4; d <<= 1) {
            M34 o = shflup(run, d, 4);
            if (lane4 >= d) run = compose(o, run);
        }
        // exclusive prefix: lane j gets lane j-1's inclusive
        M34 E = shflup(run, 1, 4);

        // wait for THIS chunk's backbone globals
        if (tid == 0) {
            while (ld_acquire(&g_cflag[chunk][0]) == 0) __nanosleep(32);
        }
        __syncthreads();

        // parent global transform directly from g_G
        M34 F;
#pragma unroll
        for (int c = 0; c < 9; c++) F.r[c] = __ldcg(&g_G[c][chain]);
#pragma unroll
        for (int c = 0; c < 3; c++) F.t[c] = __ldcg(&g_G[9 + c][chain]);
        if (lane4 != 0) F = compose(F, E);

#pragma unroll
        for (int i = 0; i < 4; i++) {
            if (i < cnt) {
                float x = tr[i][0], y = tr[i][1], z = tr[i][2];
                float vx = fmaf(F.r[0], x, fmaf(F.r[1], y, fmaf(F.r[2], z, F.t[0])));
                float vy = fmaf(F.r[3], x, fmaf(F.r[4], y, fmaf(F.r[5], z, F.t[1])));
                float vz = fmaf(F.r[6], x, fmaf(F.r[7], y, fmaf(F.r[8], z, F.t[2])));
                out[3 * kid[i] + 0] = vx;
                out[3 * kid[i] + 1] = vy;
                out[3 * kid[i] + 2] = vz;
            }
        }
    }

    // ---- final reset of all flags for graph replay ----
    // threadfence orders this block's release store(s) before the counter
    // bump, so the resetter cannot run before any flag-1 store lands.
    if (tid == 0) {
        __threadfence();
        unsigned int prev = atomicAdd(&g_cnt_all, 1u);
        if (prev == NBLK - 1) {
            g_cnt_all = 0;
            for (int i = 0; i < NBLK_BB; i++) {
                g_aflag[i][0] = 0;
                g_cflag[i][0] = 0;
            }
        }
    }
}

extern "C" void kernel_launch(void* const* d_in, const int* in_sizes, int n_in,
                              void* d_out, int out_size) {
    const float* dofs      = (const float*)d_in[0];
    const float* full_dofs = (const float*)d_in[1];
    const int*   kin_id    = (const int*)d_in[8];
    float* out = (float*)d_out;

    k_fused<<<NBLK, 128>>>(dofs, full_dofs, kin_id, out);
}

// round 14
// speedup vs baseline: 1.1750x; 1.1750x over previous
#include <cuda_runtime.h>
#include <math.h>

#define B_CHAIN 16384
#define S_SIDE  15
#define NATM    (1 + B_CHAIN + B_CHAIN * S_SIDE)
#define NBLK_BB 128
#define NBLK_SC 512
#define NBLK    (NBLK_BB + NBLK_SC)

// 3x4 affine transform: rotation r[9] row-major, translation t[3]
struct M34 { float r[9]; float t[3]; };

__device__ __forceinline__ M34 m_identity() {
    M34 m;
    m.r[0]=1.f; m.r[1]=0.f; m.r[2]=0.f;
    m.r[3]=0.f; m.r[4]=1.f; m.r[5]=0.f;
    m.r[6]=0.f; m.r[7]=0.f; m.r[8]=1.f;
    m.t[0]=0.f; m.t[1]=0.f; m.t[2]=0.f;
    return m;
}

// C = A @ B  (A is the earlier transform)
__device__ __forceinline__ M34 compose(const M34& A, const M34& B) {
    M34 C;
#pragma unroll
    for (int i = 0; i < 3; i++) {
#pragma unroll
        for (int j = 0; j < 3; j++) {
            C.r[i*3+j] = fmaf(A.r[i*3+0], B.r[0*3+j],
                          fmaf(A.r[i*3+1], B.r[1*3+j],
                               A.r[i*3+2] * B.r[2*3+j]));
        }
        C.t[i] = fmaf(A.r[i*3+0], B.t[0],
                  fmaf(A.r[i*3+1], B.t[1],
                   fmaf(A.r[i*3+2], B.t[2], A.t[i])));
    }
    return C;
}

__device__ __forceinline__ M34 shflup(const M34& v, int d, int width) {
    M34 o;
#pragma unroll
    for (int k = 0; k < 9; k++) o.r[k] = __shfl_up_sync(0xffffffffu, v.r[k], d, width);
#pragma unroll
    for (int k = 0; k < 3; k++) o.t[k] = __shfl_up_sync(0xffffffffu, v.t[k], d, width);
    return o;
}

__device__ __forceinline__ M34 shfldown(const M34& v, int d) {
    M34 o;
#pragma unroll
    for (int k = 0; k < 9; k++) o.r[k] = __shfl_down_sync(0xffffffffu, v.r[k], d);
#pragma unroll
    for (int k = 0; k < 3; k++) o.t[k] = __shfl_down_sync(0xffffffffu, v.t[k], d);
    return o;
}

// FMA-pipe sincos: magic-number quadrant reduction + cephes minimax polys.
// Valid for |x| << 2^22 (here |x| < 3). Max err ~1.2e-7.
__device__ __forceinline__ void poly_sincos(float x, float* sp, float* cp) {
    const float MAGIC = 12582912.0f;             // 1.5 * 2^23
    float k = fmaf(x, 0.63661977236758134f, MAGIC);
    int   q = __float_as_int(k);
    float n = k - MAGIC;
    float r = fmaf(n, -1.57079637e+00f, x);      // pi/2 hi
    r       = fmaf(n,  4.37113883e-08f, r);      // pi/2 lo correction
    float z = r * r;
    float ps = fmaf(z, fmaf(z, -1.9515295891e-4f, 8.3321608736e-3f), -1.6666654611e-1f);
    ps = fmaf(ps * z, r, r);
    float pc = fmaf(z, fmaf(z, 2.44331571e-5f, -1.38873163e-3f), 4.16666457e-2f);
    pc = fmaf(pc, z * z, fmaf(-0.5f, z, 1.0f));
    bool swap = (q & 1);
    float s = swap ? pc : ps;
    float c = swap ? ps : pc;
    if (q & 2) s = -s;
    if ((q + 1) & 2) c = -c;
    *sp = s; *cp = c;
}

// Bond matrix: Rx(a)*Rz(b)*T(c,0,0)*Rx(d) given sin/cos of the three angles.
__device__ __forceinline__ M34 bond_mat(float sa, float ca, float sb, float cb,
                                        float sd, float cd, float c) {
    M34 m;
    m.r[0] = cb;      m.r[1] = -cd * sb;                 m.r[2] = sd * sb;
    m.r[3] = ca * sb; m.r[4] = fmaf(cd*ca, cb, -sd*sa);  m.r[5] = fmaf(-sd*ca, cb, -cd*sa);
    m.r[6] = sa * sb; m.r[7] = fmaf(cd*sa, cb,  sd*ca);  m.r[8] = fmaf(-sd*sa, cb,  cd*ca);
    m.t[0] = c * cb;
    m.t[1] = c * ca * sb;
    m.t[2] = c * sa * sb;
    return m;
}

// Fast bond build (poly sincos, FMA pipe)
__device__ __forceinline__ M34 build_bond_fast(int n, const float* __restrict__ dofs) {
    float4 dv = *(const float4*)(dofs + 4 * (n - 1));
    float sa, ca, sb, cb, sd, cd;
    poly_sincos(dv.x, &sa, &ca);
    poly_sincos(dv.y, &sb, &cb);
    poly_sincos(dv.w, &sd, &cd);
    return bond_mat(sa, ca, sb, cb, sd, cd, dv.z);
}

// Jump build (only node 1)
__device__ __forceinline__ M34 build_jump(int n,
                                          const float* __restrict__ dofs,
                                          const float* __restrict__ full_dofs) {
    float4 dv = *(const float4*)(dofs + 4 * (n - 1));
    float f = full_dofs[9 * n + 4];
    float e = full_dofs[9 * n + 5];
    float sd, cd, sf, cf, se, ce;
    poly_sincos(dv.w, &sd, &cd);
    poly_sincos(f, &sf, &cf);
    poly_sincos(e, &se, &ce);
    M34 m;
    m.r[0] = ce * cf;  m.r[1] = fmaf(sd*ce, sf, -cd*se);  m.r[2] = fmaf(cd*ce, sf,  sd*se);
    m.r[3] = se * cf;  m.r[4] = fmaf(sd*se, sf,  cd*ce);  m.r[5] = fmaf(cd*se, sf, -sd*ce);
    m.r[6] = -sf;      m.r[7] = sd * cf;                  m.r[8] = cd * cf;
    m.t[0] = dv.x; m.t[1] = dv.y; m.t[2] = dv.z;
    return m;
}

// Decoupled-lookback descriptor: flag+agg+inc fit in ONE 128B line.
// flag: 0 = none, 1 = aggregate ready, 2 = inclusive ready.
struct __align__(128) Desc {
    int flag; int pad0[3];
    float agg[12];
    float inc[12];
    int pad1[4];
};

// Scratch (allocation-free: __device__ globals)
__device__ Desc  g_desc[NBLK_BB];
__device__ float g_G[12][B_CHAIN];     // backbone GLOBAL transforms (SoA)
__device__ int   g_cflag[NBLK_BB][32]; // chunk-globals-ready flags (one line each)
__device__ unsigned int g_cnt_all;     // all blocks completed (self-reset)

__device__ __forceinline__ int ld_acquire(int* p) {
    int v;
    asm volatile("ld.acquire.gpu.global.b32 %0, [%1];" : "=r"(v) : "l"(p) : "memory");
    return v;
}
__device__ __forceinline__ void st_release(int* p, int v) {
    asm volatile("st.release.gpu.global.b32 [%0], %1;" :: "l"(p), "r"(v) : "memory");
}

// Inclusive Kogge-Stone scan across 128 threads (4 warps)
__device__ __forceinline__ void block_scan_128(M34& v, int tid, M34* sAgg) {
    int lane = tid & 31, w = tid >> 5;
#pragma unroll
    for (int d = 1; d < 32; d <<= 1) {
        M34 o = shflup(v, d, 32);
        if (lane >= d) v = compose(o, v);
    }
    if (lane == 31) sAgg[w] = v;
    __syncthreads();
    if (w > 0) {
        M34 p = sAgg[0];
        for (int k = 1; k < w; k++) p = compose(p, sAgg[k]);
        v = compose(p, v);
    }
}

// Single fused kernel with DECOUPLED LOOKBACK (Merrill-Garland single-pass):
// no global barrier; backbone block b resolves its prefix by polling only
// lower-numbered blocks (deadlock-free by launch order), then releases its
// chunk -> side blocks wake progressively, pipelining the scatter phase into
// the prefix resolution instead of bursting after a full-grid barrier.
__global__ void __launch_bounds__(128, 5)
k_fused(const float* __restrict__ dofs,
        const float* __restrict__ full_dofs,
        const int* __restrict__ kin_id,
        float* __restrict__ out) {
    __shared__ M34 sAgg[4];
    __shared__ float sP[12];   // this block's exclusive prefix
    __shared__ float sA[12];   // this block's aggregate
    int blk = blockIdx.x;
    int tid = threadIdx.x;

    if (blk < NBLK_BB) {
        // ---------------- backbone ----------------
        int t = blk * 128 + tid;       // 0..16383
        int n = t + 1;                 // backbone node; n==1 is the jump node
        int kid = kin_id[n];           // prefetch
        M34 v = (n == 1) ? build_jump(n, dofs, full_dofs)
                         : build_bond_fast(n, dofs);
        block_scan_128(v, tid, sAgg);

        // publish aggregate ASAP (tid 127 holds the block aggregate)
        if (tid == 127) {
#pragma unroll
            for (int c = 0; c < 9; c++) { g_desc[blk].agg[c] = v.r[c]; sA[c] = v.r[c]; }
#pragma unroll
            for (int c = 0; c < 3; c++) { g_desc[blk].agg[9 + c] = v.t[c]; sA[9 + c] = v.t[c]; }
            st_release(&g_desc[blk].flag, 1);
        }
        __syncthreads();

        // ---- lookback (warp 0): resolve exclusive prefix ----
        if (blk == 0) {
            if (tid == 0) {
#pragma unroll
                for (int c = 0; c < 12; c++) {
                    sP[c] = (c == 0 || c == 4 || c == 8) ? 1.f : 0.f;
                    g_desc[0].inc[c] = sA[c];
                }
                st_release(&g_desc[0].flag, 2);
            }
        } else if (tid < 32) {
            M34 ex = m_identity();      // meaningful only on lane 0
            int base = blk;
            bool done = false;
            while (!done) {
                int pred = base - 1 - tid;   // lane 0 = nearest predecessor
                int st;
                M34 val;
                if (pred < 0) {
                    st = 2;
                    val = m_identity();
                } else {
                    do {
                        st = ld_acquire(&g_desc[pred].flag);
                        if (st == 0) __nanosleep(32);
                    } while (st == 0);
                    const float* src = (st == 2) ? g_desc[pred].inc : g_desc[pred].agg;
#pragma unroll
                    for (int c = 0; c < 9; c++) val.r[c] = src[c];
#pragma unroll
                    for (int c = 0; c < 3; c++) val.t[c] = src[9 + c];
                }
                unsigned mask = __ballot_sync(0xffffffffu, st == 2);
                int cut = mask ? (__ffs(mask) - 1) : 32;   // smallest lane w/ inclusive
                if (tid > cut) val = m_identity();          // mask out beyond cut
                // suffix-compose: lane0 <- val[min(cut,31)] ∘ ... ∘ val[0]
#pragma unroll
                for (int d = 1; d < 32; d <<= 1) {
                    M34 o = shfldown(val, d);
                    if (tid + d < 32) val = compose(o, val);
                }
                if (tid == 0) ex = compose(val, ex);  // window is EARLIER than accumulated
                done = (cut < 32);
                base -= 32;
            }
            if (tid == 0) {
                // publish inclusive = ex ∘ aggregate, and exclusive to smem
                M34 A;
#pragma unroll
                for (int c = 0; c < 9; c++) A.r[c] = sA[c];
#pragma unroll
                for (int c = 0; c < 3; c++) A.t[c] = sA[9 + c];
                M34 inc = compose(ex, A);
#pragma unroll
                for (int c = 0; c < 9; c++) g_desc[blk].inc[c] = inc.r[c];
#pragma unroll
                for (int c = 0; c < 3; c++) g_desc[blk].inc[9 + c] = inc.t[c];
                st_release(&g_desc[blk].flag, 2);
#pragma unroll
                for (int c = 0; c < 9; c++) sP[c] = ex.r[c];
#pragma unroll
                for (int c = 0; c < 3; c++) sP[9 + c] = ex.t[c];
            }
        }
        __syncthreads();

        // apply prefix, write g_G, release this chunk BEFORE own scatter
        M34 P;
#pragma unroll
        for (int c = 0; c < 9; c++) P.r[c] = sP[c];
#pragma unroll
        for (int c = 0; c < 3; c++) P.t[c] = sP[9 + c];
        M34 G = compose(P, v);
#pragma unroll
        for (int c = 0; c < 9; c++) g_G[c][t] = G.r[c];
#pragma unroll
        for (int c = 0; c < 3; c++) g_G[9 + c][t] = G.t[c];
        __threadfence();
        __syncthreads();
        if (tid == 0) st_release(&g_cflag[blk][0], 1);

        // own backbone coord (scattered) after release
        out[3 * kid + 0] = G.t[0];
        out[3 * kid + 1] = G.t[1];
        out[3 * kid + 2] = G.t[2];
    } else {
        // ------- side chains: 4 lanes/chain (ILP-batched builds) -------
        int sblk  = blk - NBLK_BB;           // 0..511
        int lane4 = tid & 3;
        int chain = sblk * 32 + (tid >> 2);  // 0..16383 (32 chains/block, one chunk)
        int chunk = sblk >> 2;
        int base  = lane4 * 4;
        int cnt   = (lane4 == 3) ? 3 : 4;    // 4+4+4+3 = 15 atoms
        int a0    = 1 + B_CHAIN + chain * S_SIDE + base;

        // prefetch all dv (4 independent LDG.128, clamped in-bounds)
        float4 dv[4];
#pragma unroll
        for (int i = 0; i < 4; i++) {
            int ns = a0 + i;
            if (ns > NATM - 1) ns = NATM - 1;
            dv[i] = *(const float4*)(dofs + 4 * (ns - 1));
        }
        int kid[4];
#pragma unroll
        for (int i = 0; i < 4; i++) {
            int ns = a0 + i;
            if (ns > NATM - 1) ns = NATM - 1;
            kid[i] = kin_id[ns];
        }

        // 12 independent sincos up-front (ILP)
        float sc[4][6];
#pragma unroll
        for (int i = 0; i < 4; i++) {
            poly_sincos(dv[i].x, &sc[i][0], &sc[i][1]);
            poly_sincos(dv[i].y, &sc[i][2], &sc[i][3]);
            poly_sincos(dv[i].w, &sc[i][4], &sc[i][5]);
        }

        float tr[4][3];
        M34 run = bond_mat(sc[0][0], sc[0][1], sc[0][2], sc[0][3],
                           sc[0][4], sc[0][5], dv[0].z);
        tr[0][0] = run.t[0]; tr[0][1] = run.t[1]; tr[0][2] = run.t[2];
#pragma unroll
        for (int i = 1; i < 4; i++) {
            M34 h = bond_mat(sc[i][0], sc[i][1], sc[i][2], sc[i][3],
                             sc[i][4], sc[i][5], dv[i].z);
            if (i < cnt) {
                run = compose(run, h);
                tr[i][0] = run.t[0]; tr[i][1] = run.t[1]; tr[i][2] = run.t[2];
            }
        }

        // inclusive scan over the 4 lanes of this chain
#pragma unroll
        for (int d = 1; d < 4; d <<= 1) {
            M34 o = shflup(run, d, 4);
            if (lane4 >= d) run = compose(o, run);
        }
        // exclusive prefix: lane j gets lane j-1's inclusive
        M34 E = shflup(run, 1, 4);

        // wait for THIS chunk's backbone globals (progressive wake)
        if (tid == 0) {
            while (ld_acquire(&g_cflag[chunk][0]) == 0) __nanosleep(32);
        }
        __syncthreads();

        // parent global transform directly from g_G
        M34 F;
#pragma unroll
        for (int c = 0; c < 9; c++) F.r[c] = __ldcg(&g_G[c][chain]);
#pragma unroll
        for (int c = 0; c < 3; c++) F.t[c] = __ldcg(&g_G[9 + c][chain]);
        if (lane4 != 0) F = compose(F, E);

#pragma unroll
        for (int i = 0; i < 4; i++) {
            if (i < cnt) {
                float x = tr[i][0], y = tr[i][1], z = tr[i][2];
                float vx = fmaf(F.r[0], x, fmaf(F.r[1], y, fmaf(F.r[2], z, F.t[0])));
                float vy = fmaf(F.r[3], x, fmaf(F.r[4], y, fmaf(F.r[5], z, F.t[1])));
                float vz = fmaf(F.r[6], x, fmaf(F.r[7], y, fmaf(F.r[8], z, F.t[2])));
                out[3 * kid[i] + 0] = vx;
                out[3 * kid[i] + 1] = vy;
                out[3 * kid[i] + 2] = vz;
            }
        }
    }

    // ---- final reset of all flags for graph replay ----
    if (tid == 0) {
        __threadfence();
        unsigned int prev = atomicAdd(&g_cnt_all, 1u);
        if (prev == NBLK - 1) {
            g_cnt_all = 0;
            for (int i = 0; i < NBLK_BB; i++) {
                g_desc[i].flag = 0;
                g_cflag[i][0] = 0;
            }
        }
    }
}

extern "C" void kernel_launch(void* const* d_in, const int* in_sizes, int n_in,
                              void* d_out, int out_size) {
    const float* dofs      = (const float*)d_in[0];
    const float* full_dofs = (const float*)d_in[1];
    const int*   kin_id    = (const int*)d_in[8];
    float* out = (float*)d_out;

    k_fused<<<NBLK, 128>>>(dofs, full_dofs, kin_id, out);
}

// round 15
// speedup vs baseline: 1.3378x; 1.1385x over previous
#include <cuda_runtime.h>
#include <math.h>

#define B_CHAIN 16384
#define S_SIDE  15
#define NATM    (1 + B_CHAIN + B_CHAIN * S_SIDE)
#define NBLK_BB 128
#define NBLK_SC 512
#define NBLK    (NBLK_BB + NBLK_SC)

// 3x4 affine transform: rotation r[9] row-major, translation t[3]
struct M34 { float r[9]; float t[3]; };

__device__ __forceinline__ M34 m_identity() {
    M34 m;
    m.r[0]=1.f; m.r[1]=0.f; m.r[2]=0.f;
    m.r[3]=0.f; m.r[4]=1.f; m.r[5]=0.f;
    m.r[6]=0.f; m.r[7]=0.f; m.r[8]=1.f;
    m.t[0]=0.f; m.t[1]=0.f; m.t[2]=0.f;
    return m;
}

// C = A @ B  (A is the earlier transform)
__device__ __forceinline__ M34 compose(const M34& A, const M34& B) {
    M34 C;
#pragma unroll
    for (int i = 0; i < 3; i++) {
#pragma unroll
        for (int j = 0; j < 3; j++) {
            C.r[i*3+j] = fmaf(A.r[i*3+0], B.r[0*3+j],
                          fmaf(A.r[i*3+1], B.r[1*3+j],
                               A.r[i*3+2] * B.r[2*3+j]));
        }
        C.t[i] = fmaf(A.r[i*3+0], B.t[0],
                  fmaf(A.r[i*3+1], B.t[1],
                   fmaf(A.r[i*3+2], B.t[2], A.t[i])));
    }
    return C;
}

__device__ __forceinline__ M34 shflup(const M34& v, int d, int width) {
    M34 o;
#pragma unroll
    for (int k = 0; k < 9; k++) o.r[k] = __shfl_up_sync(0xffffffffu, v.r[k], d, width);
#pragma unroll
    for (int k = 0; k < 3; k++) o.t[k] = __shfl_up_sync(0xffffffffu, v.t[k], d, width);
    return o;
}

// FMA-pipe sincos: magic-number quadrant reduction + cephes minimax polys.
// Valid for |x| << 2^22 (here |x| < 3). Max err ~1.2e-7.
__device__ __forceinline__ void poly_sincos(float x, float* sp, float* cp) {
    const float MAGIC = 12582912.0f;             // 1.5 * 2^23
    float k = fmaf(x, 0.63661977236758134f, MAGIC);
    int   q = __float_as_int(k);
    float n = k - MAGIC;
    float r = fmaf(n, -1.57079637e+00f, x);      // pi/2 hi
    r       = fmaf(n,  4.37113883e-08f, r);      // pi/2 lo correction
    float z = r * r;
    float ps = fmaf(z, fmaf(z, -1.9515295891e-4f, 8.3321608736e-3f), -1.6666654611e-1f);
    ps = fmaf(ps * z, r, r);
    float pc = fmaf(z, fmaf(z, 2.44331571e-5f, -1.38873163e-3f), 4.16666457e-2f);
    pc = fmaf(pc, z * z, fmaf(-0.5f, z, 1.0f));
    bool swap = (q & 1);
    float s = swap ? pc : ps;
    float c = swap ? ps : pc;
    if (q & 2) s = -s;
    if ((q + 1) & 2) c = -c;
    *sp = s; *cp = c;
}

// Scatter one atom's (x,y,z) to out+3*kid with TWO store instructions
// instead of three: the 8B-aligned pair goes as a single STG.64.
// 12*kid % 8 == 0 when kid even -> (x,y) pair aligned; else (y,z) pair
// at byte offset 4*(3*kid+1) is aligned.
__device__ __forceinline__ void scatter3(float* __restrict__ out, int kid,
                                         float x, float y, float z) {
    float* p = out + 3 * kid;
    if (kid & 1) {
        p[0] = x;
        *reinterpret_cast<float2*>(p + 1) = make_float2(y, z);
    } else {
        *reinterpret_cast<float2*>(p) = make_float2(x, y);
        p[2] = z;
    }
}

// Bond matrix: Rx(a)*Rz(b)*T(c,0,0)*Rx(d) given sin/cos of the three angles.
__device__ __forceinline__ M34 bond_mat(float sa, float ca, float sb, float cb,
                                        float sd, float cd, float c) {
    M34 m;
    m.r[0] = cb;      m.r[1] = -cd * sb;                 m.r[2] = sd * sb;
    m.r[3] = ca * sb; m.r[4] = fmaf(cd*ca, cb, -sd*sa);  m.r[5] = fmaf(-sd*ca, cb, -cd*sa);
    m.r[6] = sa * sb; m.r[7] = fmaf(cd*sa, cb,  sd*ca);  m.r[8] = fmaf(-sd*sa, cb,  cd*ca);
    m.t[0] = c * cb;
    m.t[1] = c * ca * sb;
    m.t[2] = c * sa * sb;
    return m;
}

// Fast bond build (poly sincos, FMA pipe)
__device__ __forceinline__ M34 build_bond_fast(int n, const float* __restrict__ dofs) {
    float4 dv = *(const float4*)(dofs + 4 * (n - 1));
    float sa, ca, sb, cb, sd, cd;
    poly_sincos(dv.x, &sa, &ca);
    poly_sincos(dv.y, &sb, &cb);
    poly_sincos(dv.w, &sd, &cd);
    return bond_mat(sa, ca, sb, cb, sd, cd, dv.z);
}

// Jump build (only node 1; e = full[n][5], f = full[n][4])
__device__ __forceinline__ M34 build_jump(int n,
                                          const float* __restrict__ dofs,
                                          const float* __restrict__ full_dofs) {
    float4 dv = *(const float4*)(dofs + 4 * (n - 1));
    float f = full_dofs[9 * n + 4];
    float e = full_dofs[9 * n + 5];
    float sd, cd, sf, cf, se, ce;
    poly_sincos(dv.w, &sd, &cd);
    poly_sincos(f, &sf, &cf);
    poly_sincos(e, &se, &ce);
    M34 m;
    m.r[0] = ce * cf;  m.r[1] = fmaf(sd*ce, sf, -cd*se);  m.r[2] = fmaf(cd*ce, sf,  sd*se);
    m.r[3] = se * cf;  m.r[4] = fmaf(sd*se, sf,  cd*ce);  m.r[5] = fmaf(cd*se, sf, -sd*ce);
    m.r[6] = -sf;      m.r[7] = sd * cf;                  m.r[8] = cd * cf;
    m.t[0] = dv.x; m.t[1] = dv.y; m.t[2] = dv.z;
    return m;
}

// Scratch (allocation-free: __device__ globals)
__device__ float g_L[12][B_CHAIN];   // backbone block-local inclusive products (SoA)
__device__ float g_Agg[128][12];     // per-backbone-block aggregates
__device__ float g_P[128][12];       // exclusive chunk prefixes
__device__ unsigned int g_cnt_bb;    // backbone blocks completed (self-reset)
__device__ unsigned int g_cnt_all;   // all blocks completed (self-reset)
__device__ int g_flag;               // g_P-ready flag (self-reset)

__device__ __forceinline__ int ld_acquire(int* p) {
    int v;
    asm volatile("ld.acquire.gpu.global.b32 %0, [%1];" : "=r"(v) : "l"(p) : "memory");
    return v;
}
__device__ __forceinline__ void st_release(int* p, int v) {
    asm volatile("st.release.gpu.global.b32 [%0], %1;" :: "l"(p), "r"(v) : "memory");
}

// Inclusive Kogge-Stone scan across 128 threads (4 warps)
__device__ __forceinline__ void block_scan_128(M34& v, int tid, M34* sAgg) {
    int lane = tid & 31, w = tid >> 5;
#pragma unroll
    for (int d = 1; d < 32; d <<= 1) {
        M34 o = shflup(v, d, 32);
        if (lane >= d) v = compose(o, v);
    }
    if (lane == 31) sAgg[w] = v;
    __syncthreads();
    if (w > 0) {
        M34 p = sAgg[0];
        for (int k = 1; k < w; k++) p = compose(p, sAgg[k]);
        v = compose(p, v);
    }
}

__device__ __forceinline__ void load_P(int row, M34& P) {
#pragma unroll
    for (int c = 0; c < 9; c++) P.r[c] = __ldcg(&g_P[row][c]);
#pragma unroll
    for (int c = 0; c < 3; c++) P.t[c] = __ldcg(&g_P[row][9 + c]);
}

// Single fused kernel (best-measured R11 structure) + paired-store scatter.
// launch_bounds(128,5): capacity 740 >= 640, all blocks co-resident.
__global__ void __launch_bounds__(128, 5)
k_fused(const float* __restrict__ dofs,
        const float* __restrict__ full_dofs,
        const int* __restrict__ kin_id,
        float* __restrict__ out) {
    __shared__ M34 sAgg[4];
    __shared__ bool sLast;
    int blk = blockIdx.x;
    int tid = threadIdx.x;

    if (blk < NBLK_BB) {
        // ---------------- backbone ----------------
        int t = blk * 128 + tid;       // 0..16383
        int n = t + 1;                 // backbone node; n==1 is the jump node
        int kid = kin_id[n];           // prefetch
        M34 v = (n == 1) ? build_jump(n, dofs, full_dofs)
                         : build_bond_fast(n, dofs);
        block_scan_128(v, tid, sAgg);
#pragma unroll
        for (int c = 0; c < 9; c++) g_L[c][t] = v.r[c];
#pragma unroll
        for (int c = 0; c < 3; c++) g_L[9 + c][t] = v.t[c];
        if (tid == 127) {
#pragma unroll
            for (int c = 0; c < 9; c++) g_Agg[blk][c] = v.r[c];
#pragma unroll
            for (int c = 0; c < 3; c++) g_Agg[blk][9 + c] = v.t[c];
        }
        __threadfence();
        __syncthreads();
        if (tid == 0) {
            unsigned int prev = atomicAdd(&g_cnt_bb, 1u);
            sLast = (prev == NBLK_BB - 1);
        }
        __syncthreads();
        if (sLast) {
            // last backbone block: scan aggregates -> g_P, publish flag
            M34 a;
#pragma unroll
            for (int c = 0; c < 9; c++) a.r[c] = __ldcg(&g_Agg[tid][c]);
#pragma unroll
            for (int c = 0; c < 3; c++) a.t[c] = __ldcg(&g_Agg[tid][9 + c]);
            block_scan_128(a, tid, sAgg);
            if (tid == 0) {
                M34 I = m_identity();
#pragma unroll
                for (int c = 0; c < 9; c++) g_P[0][c] = I.r[c];
#pragma unroll
                for (int c = 0; c < 3; c++) g_P[0][9 + c] = I.t[c];
            }
            if (tid < 127) {
#pragma unroll
                for (int c = 0; c < 9; c++) g_P[tid + 1][c] = a.r[c];
#pragma unroll
                for (int c = 0; c < 3; c++) g_P[tid + 1][9 + c] = a.t[c];
            }
            __threadfence();
            __syncthreads();
            if (tid == 0) {
                g_cnt_bb = 0;            // self-reset for graph replay
                st_release(&g_flag, 1);
            }
            __syncthreads();
        } else {
            if (tid == 0) {
                while (ld_acquire(&g_flag) == 0) __nanosleep(32);
            }
            __syncthreads();
        }
        // apply own prefix, write backbone coord (L still in regs as v)
        M34 P;
        load_P(blk, P);
        M34 G = compose(P, v);
        scatter3(out, kid, G.t[0], G.t[1], G.t[2]);
    } else {
        // ------- side chains: 4 lanes/chain, ILP-batched builds -------
        int sblk  = blk - NBLK_BB;           // 0..511
        int lane4 = tid & 3;
        int chain = sblk * 32 + (tid >> 2);  // 0..16383
        int base  = lane4 * 4;
        int cnt   = (lane4 == 3) ? 3 : 4;    // 4+4+4+3 = 15 atoms
        int a0    = 1 + B_CHAIN + chain * S_SIDE + base;

        // prefetch all dv (4 independent LDG.128, clamped in-bounds)
        float4 dv[4];
#pragma unroll
        for (int i = 0; i < 4; i++) {
            int ns = a0 + i;
            if (ns > NATM - 1) ns = NATM - 1;
            dv[i] = *(const float4*)(dofs + 4 * (ns - 1));
        }
        int kid[4];
#pragma unroll
        for (int i = 0; i < 4; i++) {
            int ns = a0 + i;
            if (ns > NATM - 1) ns = NATM - 1;
            kid[i] = kin_id[ns];
        }

        // 12 independent sincos up-front (ILP)
        float sc[4][6];
#pragma unroll
        for (int i = 0; i < 4; i++) {
            poly_sincos(dv[i].x, &sc[i][0], &sc[i][1]);
            poly_sincos(dv[i].y, &sc[i][2], &sc[i][3]);
            poly_sincos(dv[i].w, &sc[i][4], &sc[i][5]);
        }

        float tr[4][3];
        M34 run = bond_mat(sc[0][0], sc[0][1], sc[0][2], sc[0][3],
                           sc[0][4], sc[0][5], dv[0].z);
        tr[0][0] = run.t[0]; tr[0][1] = run.t[1]; tr[0][2] = run.t[2];
#pragma unroll
        for (int i = 1; i < 4; i++) {
            M34 h = bond_mat(sc[i][0], sc[i][1], sc[i][2], sc[i][3],
                             sc[i][4], sc[i][5], dv[i].z);
            if (i < cnt) {
                run = compose(run, h);
                tr[i][0] = run.t[0]; tr[i][1] = run.t[1]; tr[i][2] = run.t[2];
            }
        }

        // inclusive scan over the 4 lanes of this chain
#pragma unroll
        for (int d = 1; d < 4; d <<= 1) {
            M34 o = shflup(run, d, 4);
            if (lane4 >= d) run = compose(o, run);
        }
        // exclusive prefix: lane j gets lane j-1's inclusive
        M34 E = shflup(run, 1, 4);

        // wait for backbone global prefixes
        if (tid == 0) {
            while (ld_acquire(&g_flag) == 0) __nanosleep(32);
        }
        __syncthreads();

        // parent global transform: G = g_P[chain>>7] @ g_L[chain]
        M34 P, L;
        load_P(chain >> 7, P);
#pragma unroll
        for (int c = 0; c < 9; c++) L.r[c] = __ldcg(&g_L[c][chain]);
#pragma unroll
        for (int c = 0; c < 3; c++) L.t[c] = __ldcg(&g_L[9 + c][chain]);
        M34 Gp = compose(P, L);
        M34 F = (lane4 == 0) ? Gp : compose(Gp, E);

#pragma unroll
        for (int i = 0; i < 4; i++) {
            if (i < cnt) {
                float x = tr[i][0], y = tr[i][1], z = tr[i][2];
                float vx = fmaf(F.r[0], x, fmaf(F.r[1], y, fmaf(F.r[2], z, F.t[0])));
                float vy = fmaf(F.r[3], x, fmaf(F.r[4], y, fmaf(F.r[5], z, F.t[1])));
                float vz = fmaf(F.r[6], x, fmaf(F.r[7], y, fmaf(F.r[8], z, F.t[2])));
                scatter3(out, kid[i], vx, vy, vz);
            }
        }
    }

    // ---- final reset of the flag for graph replay ----
    if (tid == 0) {
        __threadfence();
        unsigned int prev = atomicAdd(&g_cnt_all, 1u);
        if (prev == NBLK - 1) {
            g_cnt_all = 0;
            g_flag = 0;
        }
    }
}

extern "C" void kernel_launch(void* const* d_in, const int* in_sizes, int n_in,
                              void* d_out, int out_size) {
    const float* dofs      = (const float*)d_in[0];
    const float* full_dofs = (const float*)d_in[1];
    const int*   kin_id    = (const int*)d_in[8];
    float* out = (float*)d_out;

    k_fused<<<NBLK, 128>>>(dofs, full_dofs, kin_id, out);
}

// round 16
// speedup vs baseline: 1.3824x; 1.0333x over previous
#include <cuda_runtime.h>
#include <math.h>

#define B_CHAIN 16384
#define S_SIDE  15
#define NATM    (1 + B_CHAIN + B_CHAIN * S_SIDE)
#define NBLK_BB 128
#define NBLK_SC 512
#define NBLK    (NBLK_BB + NBLK_SC)

// 3x4 affine transform: rotation r[9] row-major, translation t[3]
struct M34 { float r[9]; float t[3]; };

__device__ __forceinline__ M34 m_identity() {
    M34 m;
    m.r[0]=1.f; m.r[1]=0.f; m.r[2]=0.f;
    m.r[3]=0.f; m.r[4]=1.f; m.r[5]=0.f;
    m.r[6]=0.f; m.r[7]=0.f; m.r[8]=1.f;
    m.t[0]=0.f; m.t[1]=0.f; m.t[2]=0.f;
    return m;
}

// C = A @ B  (A is the earlier transform)
__device__ __forceinline__ M34 compose(const M34& A, const M34& B) {
    M34 C;
#pragma unroll
    for (int i = 0; i < 3; i++) {
#pragma unroll
        for (int j = 0; j < 3; j++) {
            C.r[i*3+j] = fmaf(A.r[i*3+0], B.r[0*3+j],
                          fmaf(A.r[i*3+1], B.r[1*3+j],
                               A.r[i*3+2] * B.r[2*3+j]));
        }
        C.t[i] = fmaf(A.r[i*3+0], B.t[0],
                  fmaf(A.r[i*3+1], B.t[1],
                   fmaf(A.r[i*3+2], B.t[2], A.t[i])));
    }
    return C;
}

__device__ __forceinline__ M34 shflup(const M34& v, int d, int width) {
    M34 o;
#pragma unroll
    for (int k = 0; k < 9; k++) o.r[k] = __shfl_up_sync(0xffffffffu, v.r[k], d, width);
#pragma unroll
    for (int k = 0; k < 3; k++) o.t[k] = __shfl_up_sync(0xffffffffu, v.t[k], d, width);
    return o;
}

// FMA-pipe sincos: magic-number quadrant reduction + cephes minimax polys.
// Valid for |x| << 2^22 (here |x| < 3). Max err ~1.2e-7.
__device__ __forceinline__ void poly_sincos(float x, float* sp, float* cp) {
    const float MAGIC = 12582912.0f;             // 1.5 * 2^23
    float k = fmaf(x, 0.63661977236758134f, MAGIC);
    int   q = __float_as_int(k);
    float n = k - MAGIC;
    float r = fmaf(n, -1.57079637e+00f, x);      // pi/2 hi
    r       = fmaf(n,  4.37113883e-08f, r);      // pi/2 lo correction
    float z = r * r;
    float ps = fmaf(z, fmaf(z, -1.9515295891e-4f, 8.3321608736e-3f), -1.6666654611e-1f);
    ps = fmaf(ps * z, r, r);
    float pc = fmaf(z, fmaf(z, 2.44331571e-5f, -1.38873163e-3f), 4.16666457e-2f);
    pc = fmaf(pc, z * z, fmaf(-0.5f, z, 1.0f));
    bool swap = (q & 1);
    float s = swap ? pc : ps;
    float c = swap ? ps : pc;
    if (q & 2) s = -s;
    if ((q + 1) & 2) c = -c;
    *sp = s; *cp = c;
}

// Paired-store scatter: 2 store instructions per atom instead of 3.
__device__ __forceinline__ void scatter3(float* __restrict__ out, int kid,
                                         float x, float y, float z) {
    float* p = out + 3 * kid;
    if (kid & 1) {
        p[0] = x;
        *reinterpret_cast<float2*>(p + 1) = make_float2(y, z);
    } else {
        *reinterpret_cast<float2*>(p) = make_float2(x, y);
        p[2] = z;
    }
}

// Bond matrix: Rx(a)*Rz(b)*T(c,0,0)*Rx(d) given sin/cos of the three angles.
__device__ __forceinline__ M34 bond_mat(float sa, float ca, float sb, float cb,
                                        float sd, float cd, float c) {
    M34 m;
    m.r[0] = cb;      m.r[1] = -cd * sb;                 m.r[2] = sd * sb;
    m.r[3] = ca * sb; m.r[4] = fmaf(cd*ca, cb, -sd*sa);  m.r[5] = fmaf(-sd*ca, cb, -cd*sa);
    m.r[6] = sa * sb; m.r[7] = fmaf(cd*sa, cb,  sd*ca);  m.r[8] = fmaf(-sd*sa, cb,  cd*ca);
    m.t[0] = c * cb;
    m.t[1] = c * ca * sb;
    m.t[2] = c * sa * sb;
    return m;
}

// Fast bond build (poly sincos, FMA pipe)
__device__ __forceinline__ M34 build_bond_fast(int n, const float* __restrict__ dofs) {
    float4 dv = *(const float4*)(dofs + 4 * (n - 1));
    float sa, ca, sb, cb, sd, cd;
    poly_sincos(dv.x, &sa, &ca);
    poly_sincos(dv.y, &sb, &cb);
    poly_sincos(dv.w, &sd, &cd);
    return bond_mat(sa, ca, sb, cb, sd, cd, dv.z);
}

// Jump build (only node 1; e = full[n][5], f = full[n][4])
__device__ __forceinline__ M34 build_jump(int n,
                                          const float* __restrict__ dofs,
                                          const float* __restrict__ full_dofs) {
    float4 dv = *(const float4*)(dofs + 4 * (n - 1));
    float f = full_dofs[9 * n + 4];
    float e = full_dofs[9 * n + 5];
    float sd, cd, sf, cf, se, ce;
    poly_sincos(dv.w, &sd, &cd);
    poly_sincos(f, &sf, &cf);
    poly_sincos(e, &se, &ce);
    M34 m;
    m.r[0] = ce * cf;  m.r[1] = fmaf(sd*ce, sf, -cd*se);  m.r[2] = fmaf(cd*ce, sf,  sd*se);
    m.r[3] = se * cf;  m.r[4] = fmaf(sd*se, sf,  cd*ce);  m.r[5] = fmaf(cd*se, sf, -sd*ce);
    m.r[6] = -sf;      m.r[7] = sd * cf;                  m.r[8] = cd * cf;
    m.t[0] = dv.x; m.t[1] = dv.y; m.t[2] = dv.z;
    return m;
}

// Scratch (allocation-free: __device__ globals)
__device__ float g_L[12][B_CHAIN];      // backbone block-local inclusive products (SoA)
__device__ float g_Agg[128][12];        // per-backbone-block aggregates
__device__ float g_P[128][12];          // exclusive chunk prefixes
__device__ int   g_lflag[NBLK_BB][32];  // per-chunk g_L-ready flags (one line each)
__device__ unsigned int g_cnt_bb;       // backbone blocks completed (self-reset)
__device__ unsigned int g_cnt_all;      // all blocks completed (self-reset)
__device__ int g_flag;                  // g_P-ready flag (self-reset)

__device__ __forceinline__ int ld_acquire(int* p) {
    int v;
    asm volatile("ld.acquire.gpu.global.b32 %0, [%1];" : "=r"(v) : "l"(p) : "memory");
    return v;
}
__device__ __forceinline__ void st_release(int* p, int v) {
    asm volatile("st.release.gpu.global.b32 [%0], %1;" :: "l"(p), "r"(v) : "memory");
}

// Inclusive Kogge-Stone scan across 128 threads (4 warps)
__device__ __forceinline__ void block_scan_128(M34& v, int tid, M34* sAgg) {
    int lane = tid & 31, w = tid >> 5;
#pragma unroll
    for (int d = 1; d < 32; d <<= 1) {
        M34 o = shflup(v, d, 32);
        if (lane >= d) v = compose(o, v);
    }
    if (lane == 31) sAgg[w] = v;
    __syncthreads();
    if (w > 0) {
        M34 p = sAgg[0];
        for (int k = 1; k < w; k++) p = compose(p, sAgg[k]);
        v = compose(p, v);
    }
}

__device__ __forceinline__ void load_P(int row, M34& P) {
#pragma unroll
    for (int c = 0; c < 9; c++) P.r[c] = __ldcg(&g_P[row][c]);
#pragma unroll
    for (int c = 0; c < 3; c++) P.t[c] = __ldcg(&g_P[row][9 + c]);
}

// Single fused kernel: R15 structure + early per-chunk g_L release so side
// blocks overlap their L-load and L∘E compose with the aggregate scan.
// launch_bounds(128,5): capacity 740 >= 640, all blocks co-resident.
__global__ void __launch_bounds__(128, 5)
k_fused(const float* __restrict__ dofs,
        const float* __restrict__ full_dofs,
        const int* __restrict__ kin_id,
        float* __restrict__ out) {
    __shared__ M34 sAgg[4];
    __shared__ bool sLast;
    int blk = blockIdx.x;
    int tid = threadIdx.x;

    if (blk < NBLK_BB) {
        // ---------------- backbone ----------------
        int t = blk * 128 + tid;       // 0..16383
        int n = t + 1;                 // backbone node; n==1 is the jump node
        int kid = kin_id[n];           // prefetch
        M34 v = (n == 1) ? build_jump(n, dofs, full_dofs)
                         : build_bond_fast(n, dofs);
        block_scan_128(v, tid, sAgg);
#pragma unroll
        for (int c = 0; c < 9; c++) g_L[c][t] = v.r[c];
#pragma unroll
        for (int c = 0; c < 3; c++) g_L[9 + c][t] = v.t[c];
        if (tid == 127) {
#pragma unroll
            for (int c = 0; c < 9; c++) g_Agg[blk][c] = v.r[c];
#pragma unroll
            for (int c = 0; c < 3; c++) g_Agg[blk][9 + c] = v.t[c];
        }
        __threadfence();
        __syncthreads();
        // EARLY per-chunk release: g_L for this chunk is ready now.
        if (tid == 64) st_release(&g_lflag[blk][0], 1);
        if (tid == 0) {
            unsigned int prev = atomicAdd(&g_cnt_bb, 1u);
            sLast = (prev == NBLK_BB - 1);
        }
        __syncthreads();
        if (sLast) {
            // last backbone block: scan aggregates -> g_P, publish flag
            M34 a;
#pragma unroll
            for (int c = 0; c < 9; c++) a.r[c] = __ldcg(&g_Agg[tid][c]);
#pragma unroll
            for (int c = 0; c < 3; c++) a.t[c] = __ldcg(&g_Agg[tid][9 + c]);
            block_scan_128(a, tid, sAgg);
            if (tid == 0) {
                M34 I = m_identity();
#pragma unroll
                for (int c = 0; c < 9; c++) g_P[0][c] = I.r[c];
#pragma unroll
                for (int c = 0; c < 3; c++) g_P[0][9 + c] = I.t[c];
            }
            if (tid < 127) {
#pragma unroll
                for (int c = 0; c < 9; c++) g_P[tid + 1][c] = a.r[c];
#pragma unroll
                for (int c = 0; c < 3; c++) g_P[tid + 1][9 + c] = a.t[c];
            }
            __threadfence();
            __syncthreads();
            if (tid == 0) {
                g_cnt_bb = 0;            // self-reset for graph replay
                st_release(&g_flag, 1);
            }
            __syncthreads();
        } else {
            if (tid == 0) {
                while (ld_acquire(&g_flag) == 0) __nanosleep(32);
            }
            __syncthreads();
        }
        // apply own prefix, write backbone coord (L still in regs as v)
        M34 P;
        load_P(blk, P);
        M34 G = compose(P, v);
        scatter3(out, kid, G.t[0], G.t[1], G.t[2]);
    } else {
        // ------- side chains: 4 lanes/chain, ILP-batched builds -------
        int sblk  = blk - NBLK_BB;           // 0..511
        int lane4 = tid & 3;
        int chain = sblk * 32 + (tid >> 2);  // 0..16383 (one chunk per block)
        int chunk = sblk >> 2;
        int base  = lane4 * 4;
        int cnt   = (lane4 == 3) ? 3 : 4;    // 4+4+4+3 = 15 atoms
        int a0    = 1 + B_CHAIN + chain * S_SIDE + base;

        // prefetch all dv (4 independent LDG.128, clamped in-bounds)
        float4 dv[4];
#pragma unroll
        for (int i = 0; i < 4; i++) {
            int ns = a0 + i;
            if (ns > NATM - 1) ns = NATM - 1;
            dv[i] = *(const float4*)(dofs + 4 * (ns - 1));
        }
        int kid[4];
#pragma unroll
        for (int i = 0; i < 4; i++) {
            int ns = a0 + i;
            if (ns > NATM - 1) ns = NATM - 1;
            kid[i] = kin_id[ns];
        }

        // 12 independent sincos up-front (ILP)
        float sc[4][6];
#pragma unroll
        for (int i = 0; i < 4; i++) {
            poly_sincos(dv[i].x, &sc[i][0], &sc[i][1]);
            poly_sincos(dv[i].y, &sc[i][2], &sc[i][3]);
            poly_sincos(dv[i].w, &sc[i][4], &sc[i][5]);
        }

        float tr[4][3];
        M34 run = bond_mat(sc[0][0], sc[0][1], sc[0][2], sc[0][3],
                           sc[0][4], sc[0][5], dv[0].z);
        tr[0][0] = run.t[0]; tr[0][1] = run.t[1]; tr[0][2] = run.t[2];
#pragma unroll
        for (int i = 1; i < 4; i++) {
            M34 h = bond_mat(sc[i][0], sc[i][1], sc[i][2], sc[i][3],
                             sc[i][4], sc[i][5], dv[i].z);
            if (i < cnt) {
                run = compose(run, h);
                tr[i][0] = run.t[0]; tr[i][1] = run.t[1]; tr[i][2] = run.t[2];
            }
        }

        // inclusive scan over the 4 lanes of this chain
#pragma unroll
        for (int d = 1; d < 4; d <<= 1) {
            M34 o = shflup(run, d, 4);
            if (lane4 >= d) run = compose(o, run);
        }
        // exclusive prefix: lane j gets lane j-1's inclusive
        M34 E = shflup(run, 1, 4);

        // ---- EARLY: wait only for this chunk's g_L, pre-compose W = L ∘ E ----
        if (tid == 0) {
            while (ld_acquire(&g_lflag[chunk][0]) == 0) __nanosleep(32);
        }
        __syncthreads();
        M34 W;   // W = L for lane 0, L ∘ E otherwise
#pragma unroll
        for (int c = 0; c < 9; c++) W.r[c] = __ldcg(&g_L[c][chain]);
#pragma unroll
        for (int c = 0; c < 3; c++) W.t[c] = __ldcg(&g_L[9 + c][chain]);
        if (lane4 != 0) W = compose(W, E);

        // precompute rotated translations relative to W (still prefix-free):
        // F = P ∘ W, so out = P ∘ (W applied to tr). Apply W now.
        float wtr[4][3];
#pragma unroll
        for (int i = 0; i < 4; i++) {
            if (i < cnt) {
                float x = tr[i][0], y = tr[i][1], z = tr[i][2];
                wtr[i][0] = fmaf(W.r[0], x, fmaf(W.r[1], y, fmaf(W.r[2], z, W.t[0])));
                wtr[i][1] = fmaf(W.r[3], x, fmaf(W.r[4], y, fmaf(W.r[5], z, W.t[1])));
                wtr[i][2] = fmaf(W.r[6], x, fmaf(W.r[7], y, fmaf(W.r[8], z, W.t[2])));
            }
        }

        // ---- wait for global prefixes, then tiny tail ----
        if (tid == 0) {
            while (ld_acquire(&g_flag) == 0) __nanosleep(32);
        }
        __syncthreads();

        M34 P;
        load_P(chunk, P);   // hot L2 line, shared by all blocks of this chunk

#pragma unroll
        for (int i = 0; i < 4; i++) {
            if (i < cnt) {
                float x = wtr[i][0], y = wtr[i][1], z = wtr[i][2];
                float vx = fmaf(P.r[0], x, fmaf(P.r[1], y, fmaf(P.r[2], z, P.t[0])));
                float vy = fmaf(P.r[3], x, fmaf(P.r[4], y, fmaf(P.r[5], z, P.t[1])));
                float vz = fmaf(P.r[6], x, fmaf(P.r[7], y, fmaf(P.r[8], z, P.t[2])));
                scatter3(out, kid[i], vx, vy, vz);
            }
        }
    }

    // ---- final reset of all flags for graph replay ----
    if (tid == 0) {
        __threadfence();
        unsigned int prev = atomicAdd(&g_cnt_all, 1u);
        if (prev == NBLK - 1) {
            g_cnt_all = 0;
            g_flag = 0;
            for (int i = 0; i < NBLK_BB; i++) g_lflag[i][0] = 0;
        }
    }
}

extern "C" void kernel_launch(void* const* d_in, const int* in_sizes, int n_in,
                              void* d_out, int out_size) {
    const float* dofs      = (const float*)d_in[0];
    const float* full_dofs = (const float*)d_in[1];
    const int*   kin_id    = (const int*)d_in[8];
    float* out = (float*)d_out;

    k_fused<<<NBLK, 128>>>(dofs, full_dofs, kin_id, out);
}